// round 6
// baseline (speedup 1.0000x reference)
#include <cuda_runtime.h>
#include <cuda_bf16.h>
#include <cstdint>

// out = x @ Weff + bias;  Weff[8m+p, f] = sum_k scale[k,f]*sign(bit(7-p) of binary[k,m,f])
// Split-bf16 HMMA path: out = Ah*Bh + Al*Bh + Ah*Bl (fused accumulator),
// split-K=6 with STG partials + reduce (no atomics).

#define NX 768
#define NF 768
#define NM 256
#define NG 96

#define SPLITS 6
#define BKC 128          // k per CTA = NX / SPLITS
#define ROWP 136         // 128 + 8 halves pad -> conflict-free ldmatrix

__device__ __nv_bfloat16 g_ah[NM * NX];
__device__ __nv_bfloat16 g_al[NM * NX];
__device__ __nv_bfloat16 g_bh[NF * NX];   // [f][k]
__device__ __nv_bfloat16 g_bl[NF * NX];
__device__ float g_part[SPLITS * NM * NF];

// ---------------------------------------------------------------------------
union B2U { __nv_bfloat162 h2; uint32_t u; };
__device__ __forceinline__ uint32_t pk2(__nv_bfloat16 a, __nv_bfloat16 b) {
    B2U t; t.h2 = __halves2bfloat162(a, b); return t.u;
}
__device__ __forceinline__ uint32_t smem_u32(const void* p) {
    uint32_t a;
    asm("{ .reg .u64 t; cvta.to.shared.u64 t, %1; cvt.u32.u64 %0, t; }"
        : "=r"(a) : "l"(p));
    return a;
}
__device__ __forceinline__ void cp16(uint32_t s, const void* g) {
    asm volatile("cp.async.cg.shared.global [%0], [%1], 16;" :: "r"(s), "l"(g));
}

#define LDSM4(r, addr) \
    asm volatile("ldmatrix.sync.aligned.m8n8.x4.shared.b16 {%0,%1,%2,%3}, [%4];" \
                 : "=r"((r)[0]), "=r"((r)[1]), "=r"((r)[2]), "=r"((r)[3]) : "r"(addr))

#define MMA16816(c, a, bb0, bb1) \
    asm volatile("mma.sync.aligned.m16n8k16.row.col.f32.bf16.bf16.f32 " \
                 "{%0,%1,%2,%3}, {%4,%5,%6,%7}, {%8,%9}, {%0,%1,%2,%3};" \
                 : "+f"((c)[0]), "+f"((c)[1]), "+f"((c)[2]), "+f"((c)[3]) \
                 : "r"((a)[0]), "r"((a)[1]), "r"((a)[2]), "r"((a)[3]), \
                   "r"(bb0), "r"(bb1))

// ---------------------------------------------------------------------------
// Kernel 1 (fused prep, vectorized):
//   blocks [0,144): build Bh/Bl — 4 features per thread, int4/float4 loads
//   blocks [144,336): split x -> Ah/Al — 2 float4 per thread
// ---------------------------------------------------------------------------
#define NB_BUILD 144      // 73728/4/128
#define NB_X     192      // 49152/2/128

__global__ __launch_bounds__(128)
void prep_kernel(const float* __restrict__ scale,
                 const int*   __restrict__ binary,
                 const float* __restrict__ x) {
    const int b = blockIdx.x, tid = threadIdx.x;

    if (b < NB_BUILD) {
        const int t  = b * 128 + tid;    // < 18432
        const int fq = t % 192;          // f / 4
        const int m  = t / 192;          // 0..95
        const int f  = fq * 4;

        // front-batched wide loads: 8 x int4 + 8 x float4
        int4   c4[8];
        float4 s4[8];
#pragma unroll
        for (int k = 0; k < 8; k++) {
            c4[k] = *(const int4*)  (binary + (size_t)(k * NG + m) * NF + f);
            s4[k] = *(const float4*)(scale  + (size_t)k * NF + f);
        }

#pragma unroll
        for (int j = 0; j < 4; j++) {
            float w[8];
#pragma unroll
            for (int p = 0; p < 8; p++) w[p] = 0.0f;
#pragma unroll
            for (int k = 0; k < 8; k++) {
                const int   cc = (j == 0) ? c4[k].x : (j == 1) ? c4[k].y
                               : (j == 2) ? c4[k].z : c4[k].w;
                const float ss = (j == 0) ? s4[k].x : (j == 1) ? s4[k].y
                               : (j == 2) ? s4[k].z : s4[k].w;
#pragma unroll
                for (int p = 0; p < 8; p++)
                    w[p] += ((cc >> (7 - p)) & 1) ? ss : -ss;
            }
            __nv_bfloat16 hi[8], lo[8];
#pragma unroll
            for (int p = 0; p < 8; p++) {
                hi[p] = __float2bfloat16(w[p]);
                lo[p] = __float2bfloat16(w[p] - __bfloat162float(hi[p]));
            }
            *(uint4*)(g_bh + (size_t)(f + j) * NX + 8 * m) =
                make_uint4(pk2(hi[0], hi[1]), pk2(hi[2], hi[3]),
                           pk2(hi[4], hi[5]), pk2(hi[6], hi[7]));
            *(uint4*)(g_bl + (size_t)(f + j) * NX + 8 * m) =
                make_uint4(pk2(lo[0], lo[1]), pk2(lo[2], lo[3]),
                           pk2(lo[4], lo[5]), pk2(lo[6], lo[7]));
        }
    } else {
        const int t = (b - NB_BUILD) * 128 + tid;   // < 24576
#pragma unroll
        for (int u = 0; u < 2; u++) {
            const int i = t * 2 + u;                // float4 index < 49152
            float4 v = ((const float4*)x)[i];
            __nv_bfloat16 h0 = __float2bfloat16(v.x), h1 = __float2bfloat16(v.y);
            __nv_bfloat16 h2 = __float2bfloat16(v.z), h3 = __float2bfloat16(v.w);
            __nv_bfloat16 l0 = __float2bfloat16(v.x - __bfloat162float(h0));
            __nv_bfloat16 l1 = __float2bfloat16(v.y - __bfloat162float(h1));
            __nv_bfloat16 l2 = __float2bfloat16(v.z - __bfloat162float(h2));
            __nv_bfloat16 l3 = __float2bfloat16(v.w - __bfloat162float(h3));
            ((uint2*)g_ah)[i] = make_uint2(pk2(h0, h1), pk2(h2, h3));
            ((uint2*)g_al)[i] = make_uint2(pk2(l0, l1), pk2(l2, l3));
        }
    }
}

// ---------------------------------------------------------------------------
// Kernel 2: fused-segment HMMA GEMM, split-K partials.
// Grid (12 n, 4 m, 6 split) = 288 CTAs x 256 thr (8 warps, warp tile 16x32).
// ---------------------------------------------------------------------------
#define SM_T (64 * ROWP)             // halves per tile
#define SMEM_BYTES (4 * SM_T * 2)    // 69632

__global__ __launch_bounds__(256)
void gemm_mma_kernel() {
    extern __shared__ __align__(16) __nv_bfloat16 sm[];

    const int tid  = threadIdx.x;
    const int wid  = tid >> 5;
    const int lane = tid & 31;

    const int f0 = blockIdx.x * 64;
    const int m0 = blockIdx.y * 64;
    const int k0 = blockIdx.z * BKC;

    const __nv_bfloat16* gAH = g_ah + (size_t)m0 * NX + k0;
    const __nv_bfloat16* gAL = g_al + (size_t)m0 * NX + k0;
    const __nv_bfloat16* gBH = g_bh + (size_t)f0 * NX + k0;
    const __nv_bfloat16* gBL = g_bl + (size_t)f0 * NX + k0;

    // load all four 64x128 tiles (16 cp.async x 16B per thread)
#pragma unroll
    for (int j = 0; j < 4; j++) {
        int idx = tid + 256 * j;         // 0..1023
        int r = idx >> 4, c8 = (idx & 15) * 8;
        size_t go = (size_t)r * NX + c8;
        uint32_t so = smem_u32(sm) + (uint32_t)(r * ROWP + c8) * 2;
        cp16(so,                   gAH + go);
        cp16(so + SM_T * 2,        gAL + go);
        cp16(so + 2 * SM_T * 2,    gBH + go);
        cp16(so + 3 * SM_T * 2,    gBL + go);
    }
    asm volatile("cp.async.commit_group;" ::: "memory");

    const int wm = (wid >> 1) * 16;   // 4 warps along m
    const int wn = (wid & 1) * 32;    // 2 warps along n

    float acc[4][4];
#pragma unroll
    for (int j = 0; j < 4; j++)
#pragma unroll
        for (int v = 0; v < 4; v++) acc[j][v] = 0.0f;

    asm volatile("cp.async.wait_group 0;" ::: "memory");
    __syncthreads();

    const int ra  = wm + (lane & 15);
    const int rb0 = wn + (lane & 15);
    const uint32_t smb = smem_u32(sm);

#pragma unroll
    for (int ks = 0; ks < 8; ks++) {
        const int c = ks * 16 + ((lane >> 4) << 3);
        uint32_t ah[4], al[4], bh0[4], bh1[4], bl0[4], bl1[4];
        LDSM4(ah,  smb + (uint32_t)(ra * ROWP + c) * 2);
        LDSM4(al,  smb + (uint32_t)(SM_T + ra * ROWP + c) * 2);
        LDSM4(bh0, smb + (uint32_t)(2 * SM_T + rb0 * ROWP + c) * 2);
        LDSM4(bh1, smb + (uint32_t)(2 * SM_T + (rb0 + 16) * ROWP + c) * 2);
        LDSM4(bl0, smb + (uint32_t)(3 * SM_T + rb0 * ROWP + c) * 2);
        LDSM4(bl1, smb + (uint32_t)(3 * SM_T + (rb0 + 16) * ROWP + c) * 2);

        MMA16816(acc[0], ah, bh0[0], bh0[2]);
        MMA16816(acc[1], ah, bh0[1], bh0[3]);
        MMA16816(acc[2], ah, bh1[0], bh1[2]);
        MMA16816(acc[3], ah, bh1[1], bh1[3]);

        MMA16816(acc[0], al, bh0[0], bh0[2]);
        MMA16816(acc[1], al, bh0[1], bh0[3]);
        MMA16816(acc[2], al, bh1[0], bh1[2]);
        MMA16816(acc[3], al, bh1[1], bh1[3]);

        MMA16816(acc[0], ah, bl0[0], bl0[2]);
        MMA16816(acc[1], ah, bl0[1], bl0[3]);
        MMA16816(acc[2], ah, bl1[0], bl1[2]);
        MMA16816(acc[3], ah, bl1[1], bl1[3]);
    }

    // store partials (plain STG.64, no atomics)
    float* P = g_part + (size_t)blockIdx.z * (NM * NF);
    const int rbase = m0 + wm + (lane >> 2);
    const int cbase = f0 + wn + (lane & 3) * 2;
#pragma unroll
    for (int ni = 0; ni < 4; ni++) {
        int col = cbase + ni * 8;
        *(float2*)(P + (size_t)rbase * NF + col)       = make_float2(acc[ni][0], acc[ni][1]);
        *(float2*)(P + (size_t)(rbase + 8) * NF + col) = make_float2(acc[ni][2], acc[ni][3]);
    }
}

// ---------------------------------------------------------------------------
// Kernel 3: reduce 6 partials + bias -> out. 49152 float4 lanes.
// ---------------------------------------------------------------------------
__global__ __launch_bounds__(256)
void reduce_kernel(const float* __restrict__ bias, float* __restrict__ out) {
    const int idx = blockIdx.x * 256 + threadIdx.x;   // < NM*NF/4
    float4 p[SPLITS];
#pragma unroll
    for (int s = 0; s < SPLITS; s++)
        p[s] = ((const float4*)g_part)[s * (NM * NF / 4) + idx];
    float4 v = ((const float4*)bias)[idx % (NF / 4)];
#pragma unroll
    for (int s = 0; s < SPLITS; s++) {
        v.x += p[s].x; v.y += p[s].y; v.z += p[s].z; v.w += p[s].w;
    }
    ((float4*)out)[idx] = v;
}

// ---------------------------------------------------------------------------
extern "C" void kernel_launch(void* const* d_in, const int* in_sizes, int n_in,
                              void* d_out, int out_size) {
    const float* x      = (const float*)d_in[0];
    const float* scale  = (const float*)d_in[1];
    const int*   binary = (const int*)  d_in[2];
    const float* bias   = (const float*)d_in[3];
    float*       out    = (float*)d_out;

    cudaFuncSetAttribute(gemm_mma_kernel,
                         cudaFuncAttributeMaxDynamicSharedMemorySize, SMEM_BYTES);

    prep_kernel<<<NB_BUILD + NB_X, 128>>>(scale, binary, x);

    dim3 grid(NF / 64, NM / 64, SPLITS);   // 12 x 4 x 6 = 288 CTAs
    gemm_mma_kernel<<<grid, 256, SMEM_BYTES>>>();

    reduce_kernel<<<NM * NF / 4 / 256, 256>>>(bias, out);
}